// round 2
// baseline (speedup 1.0000x reference)
#include <cuda_runtime.h>
#include <cuda_bf16.h>

// ---------------------------------------------------------------------------
// SparseQuantLinear: out[m,n] = sum_k x[m,k] * W[n,k] + bias[n]
// W[n,k] = mask[n,k] ? (Wq[n,k]-zeros[n,k/G])*scales[n,k/G]*scale2[k] : 0
// M=16384, N=4096, K=4096, G=128 (derived at runtime from in_sizes).
//
// Round 1: fix macro token-pasting build error (no logic change).
// dequant -> 64MB __device__ scratch, then fp32 SGEMM
// (128x128x16 tile, 8x8/thread, double-buffered smem).
// ---------------------------------------------------------------------------

#define MAX_OI (4096u * 4096u)
__device__ float g_W[MAX_OI];     // dequantized weights [O, I] row-major
__device__ int   g_mask_mode;     // 0 = int32 mask, 1 = byte mask, 2 = float mask

// --- deterministic mask-dtype detection -----------------------------------
__global__ void detect_mask_kernel(const unsigned* __restrict__ m, int nwords) {
    __shared__ int s_mode;
    if (threadIdx.x == 0) s_mode = 0;
    __syncthreads();
    int mode = 0;
    for (int i = threadIdx.x; i < nwords; i += blockDim.x) {
        unsigned v = m[i];
        if (v == 0x3F800000u) { if (mode < 2) mode = 2; }
        else if (v > 1u)      { if (mode < 1) mode = 1; }
    }
    if (mode) atomicMax(&s_mode, mode);
    __syncthreads();
    if (threadIdx.x == 0) g_mask_mode = s_mode;
}

// --- dequant: O(N*K), memory bound, negligible vs GEMM --------------------
__global__ void dequant_kernel(const int* __restrict__ Wq,
                               const float* __restrict__ scales,
                               const float* __restrict__ zeros,
                               const void* __restrict__ mask,
                               const float* __restrict__ scale2,
                               int O, int I, int G) {
    int idx = blockIdx.x * blockDim.x + threadIdx.x;
    int total = O * I;
    if (idx >= total) return;
    int n = idx / I;
    int k = idx - n * I;
    int gi = n * (I / G) + k / G;
    float w = ((float)Wq[idx] - zeros[gi]) * scales[gi] * scale2[k];
    int mode = g_mask_mode;
    bool mk;
    if (mode == 1)      mk = ((const unsigned char*)mask)[idx] != 0;
    else if (mode == 2) mk = ((const float*)mask)[idx] != 0.0f;
    else                mk = ((const int*)mask)[idx] != 0;
    g_W[idx] = mk ? w : 0.0f;
}

// --- SGEMM: C[M,N] = A[M,K] @ W[N,K]^T + bias -----------------------------
constexpr int BM = 128;
constexpr int BN = 128;
constexpr int BK = 16;

__global__ __launch_bounds__(256)
void sgemm_bias_kernel(const float* __restrict__ A,
                       const float* __restrict__ bias,
                       float* __restrict__ C,
                       int M, int N, int K) {
    __shared__ float As[2][BK][BM + 4];
    __shared__ float Bs[2][BK][BN + 4];

    const float* __restrict__ Bmat = g_W;

    const int tid = threadIdx.x;
    const int bm = blockIdx.y * BM;
    const int bn = blockIdx.x * BN;
    const int tx = tid & 15;   // 0..15 -> N direction
    const int ty = tid >> 4;   // 0..15 -> M direction

    // global->smem load mapping: 256 threads x 2 float4 per matrix
    const int lrow = tid >> 2;         // 0..63 (plus +64 second half)
    const int lcol = (tid & 3) << 2;   // 0,4,8,12

    const float* Ap0 = A    + (long)(bm + lrow) * K + lcol;
    const float* Ap1 = Ap0  + (long)64 * K;
    const float* Bp0 = Bmat + (long)(bn + lrow) * K + lcol;
    const float* Bp1 = Bp0  + (long)64 * K;

    float acc[8][8];
#pragma unroll
    for (int i = 0; i < 8; i++)
#pragma unroll
        for (int j = 0; j < 8; j++) acc[i][j] = 0.0f;

    float4 ra[2], rb[2];

    // store staged registers into smem buffer b (transposed: [k][row])
    auto sts_tile = [&](int b) {
        As[b][lcol + 0][lrow]      = ra[0].x;
        As[b][lcol + 1][lrow]      = ra[0].y;
        As[b][lcol + 2][lrow]      = ra[0].z;
        As[b][lcol + 3][lrow]      = ra[0].w;
        As[b][lcol + 0][lrow + 64] = ra[1].x;
        As[b][lcol + 1][lrow + 64] = ra[1].y;
        As[b][lcol + 2][lrow + 64] = ra[1].z;
        As[b][lcol + 3][lrow + 64] = ra[1].w;
        Bs[b][lcol + 0][lrow]      = rb[0].x;
        Bs[b][lcol + 1][lrow]      = rb[0].y;
        Bs[b][lcol + 2][lrow]      = rb[0].z;
        Bs[b][lcol + 3][lrow]      = rb[0].w;
        Bs[b][lcol + 0][lrow + 64] = rb[1].x;
        Bs[b][lcol + 1][lrow + 64] = rb[1].y;
        Bs[b][lcol + 2][lrow + 64] = rb[1].z;
        Bs[b][lcol + 3][lrow + 64] = rb[1].w;
    };

    // prologue: tile 0 into buffer 0
    ra[0] = *(const float4*)(Ap0);
    ra[1] = *(const float4*)(Ap1);
    rb[0] = *(const float4*)(Bp0);
    rb[1] = *(const float4*)(Bp1);
    sts_tile(0);
    __syncthreads();

    const int nk = K / BK;
    int buf = 0;
    for (int kt = 0; kt < nk; kt++) {
        const bool has_next = (kt + 1) < nk;
        if (has_next) {
            const int ko = (kt + 1) * BK;
            ra[0] = *(const float4*)(Ap0 + ko);
            ra[1] = *(const float4*)(Ap1 + ko);
            rb[0] = *(const float4*)(Bp0 + ko);
            rb[1] = *(const float4*)(Bp1 + ko);
        }
#pragma unroll
        for (int k = 0; k < BK; k++) {
            float a[8], b[8];
            *(float4*)&a[0] = *(const float4*)&As[buf][k][ty * 4];
            *(float4*)&a[4] = *(const float4*)&As[buf][k][64 + ty * 4];
            *(float4*)&b[0] = *(const float4*)&Bs[buf][k][tx * 4];
            *(float4*)&b[4] = *(const float4*)&Bs[buf][k][64 + tx * 4];
#pragma unroll
            for (int i = 0; i < 8; i++)
#pragma unroll
                for (int j = 0; j < 8; j++)
                    acc[i][j] += a[i] * b[j];
        }
        if (has_next) {
            const int nb = buf ^ 1;
            sts_tile(nb);
            __syncthreads();
            buf = nb;
        }
    }

    // epilogue: add bias, store float4
    float bb[8];
#pragma unroll
    for (int j = 0; j < 4; j++) {
        bb[j]     = bias[bn + tx * 4 + j];
        bb[4 + j] = bias[bn + 64 + tx * 4 + j];
    }
#pragma unroll
    for (int i = 0; i < 8; i++) {
        const int row = bm + ((i < 4) ? (ty * 4 + i) : (64 + ty * 4 + (i - 4)));
        float* Cr = C + (long)row * N + bn;
        float4 v0 = make_float4(acc[i][0] + bb[0], acc[i][1] + bb[1],
                                acc[i][2] + bb[2], acc[i][3] + bb[3]);
        float4 v1 = make_float4(acc[i][4] + bb[4], acc[i][5] + bb[5],
                                acc[i][6] + bb[6], acc[i][7] + bb[7]);
        *(float4*)(Cr + tx * 4)      = v0;
        *(float4*)(Cr + 64 + tx * 4) = v1;
    }
}

// ---------------------------------------------------------------------------
extern "C" void kernel_launch(void* const* d_in, const int* in_sizes, int n_in,
                              void* d_out, int out_size) {
    // metadata order: x, W_q, scales, zeros, mask, scale2, bias, group_size
    const float* x      = (const float*)d_in[0];
    const int*   Wq     = (const int*)d_in[1];
    const float* scales = (const float*)d_in[2];
    const float* zeros  = (const float*)d_in[3];
    const void*  mask   = d_in[4];
    const float* scale2 = (const float*)d_in[5];
    const float* bias   = (const float*)d_in[6];
    float* out = (float*)d_out;

    const int I = in_sizes[5];                 // scale2: [I]
    const int O = in_sizes[6];                 // bias:   [O]
    const int M = in_sizes[0] / I;             // x: [B*S, I]
    const int ngroups = in_sizes[2] / O;       // scales: [O, I/G]
    const int G = I / ngroups;

    // 1) detect mask dtype (deterministic, same result every launch)
    int nwords = O * I / 4;
    if (nwords > (1 << 16)) nwords = (1 << 16);
    detect_mask_kernel<<<1, 256>>>((const unsigned*)mask, nwords);

    // 2) dequantize W into scratch
    const int total = O * I;
    dequant_kernel<<<(total + 255) / 256, 256>>>(Wq, scales, zeros, mask,
                                                 scale2, O, I, G);

    // 3) GEMM + bias
    dim3 grid(O / BN, M / BM);
    sgemm_bias_kernel<<<grid, 256>>>(x, bias, out, M, O, I);
}

// round 4
// speedup vs baseline: 2.9557x; 2.9557x over previous
#include <cuda_runtime.h>
#include <cuda_bf16.h>
#include <cstdint>

// ---------------------------------------------------------------------------
// SparseQuantLinear: out = x @ W^T + bias, W = mask?(Wq-z)*s*s2:0
// M=16384, N=4096, K=4096.
// R4: ptxas target is plain sm_103 (no 'a') -> tcgen05 unavailable.
// Use mma.sync.m16n8k16 bf16 (baseline PTX) with 3-term precision split:
//   out ≈ xh*Wh + xh*Wl + xl*Wh, fp32 accum (xl*Wl dropped, ~2^-18).
// BM=128,BN=128,BK=32, 4-stage cp.async pipeline, ldmatrix + SW128 swizzle.
// ---------------------------------------------------------------------------

#define MAX_M 16384u
#define MAX_K 4096u
#define MAX_O 4096u

__device__ __nv_bfloat16 g_Ah[(size_t)MAX_M * MAX_K];
__device__ __nv_bfloat16 g_Al[(size_t)MAX_M * MAX_K];
__device__ __nv_bfloat16 g_Wh[(size_t)MAX_O * MAX_K];
__device__ __nv_bfloat16 g_Wl[(size_t)MAX_O * MAX_K];
__device__ int g_mask_mode;   // 0 int32 / 1 byte / 2 float mask

// ===================== prep kernels ========================================
__global__ void detect_mask_kernel(const unsigned* __restrict__ m, int nwords) {
    __shared__ int s_mode;
    if (threadIdx.x == 0) s_mode = 0;
    __syncthreads();
    int mode = 0;
    for (int i = threadIdx.x; i < nwords; i += blockDim.x) {
        unsigned v = m[i];
        if (v == 0x3F800000u) { if (mode < 2) mode = 2; }
        else if (v > 1u)      { if (mode < 1) mode = 1; }
    }
    if (mode) atomicMax(&s_mode, mode);
    __syncthreads();
    if (threadIdx.x == 0) g_mask_mode = s_mode;
}

__global__ void split_x_kernel(const float* __restrict__ x, int total4) {
    int i = blockIdx.x * blockDim.x + threadIdx.x;
    if (i >= total4) return;
    float4 v = ((const float4*)x)[i];
    float vv[4] = {v.x, v.y, v.z, v.w};
    __nv_bfloat16 h4[4], l4[4];
#pragma unroll
    for (int j = 0; j < 4; j++) {
        h4[j] = __float2bfloat16(vv[j]);
        l4[j] = __float2bfloat16(vv[j] - __bfloat162float(h4[j]));
    }
    ((uint2*)g_Ah)[i] = *(uint2*)h4;
    ((uint2*)g_Al)[i] = *(uint2*)l4;
}

__global__ void dequant_split_kernel(const int* __restrict__ Wq,
                                     const float* __restrict__ scales,
                                     const float* __restrict__ zeros,
                                     const void* __restrict__ mask,
                                     const float* __restrict__ scale2,
                                     int O, int I, int G) {
    int i4 = blockIdx.x * blockDim.x + threadIdx.x;     // 4 elems / thread
    int total4 = O * I / 4;
    if (i4 >= total4) return;
    int idx0 = i4 * 4;
    int n = idx0 / I;
    int k0 = idx0 - n * I;
    int gi = n * (I / G) + k0 / G;                      // G>=4 so same group
    float z = zeros[gi], s = scales[gi];
    int4 q = ((const int4*)Wq)[i4];
    float4 s2 = *(const float4*)(scale2 + k0);
    int mode = g_mask_mode;
    float w[4];
    w[0] = ((float)q.x - z) * s * s2.x;
    w[1] = ((float)q.y - z) * s * s2.y;
    w[2] = ((float)q.z - z) * s * s2.z;
    w[3] = ((float)q.w - z) * s * s2.w;
    bool mk[4];
    if (mode == 1) {
        const unsigned char* mp = (const unsigned char*)mask + idx0;
        mk[0] = mp[0]; mk[1] = mp[1]; mk[2] = mp[2]; mk[3] = mp[3];
    } else if (mode == 2) {
        float4 mv = ((const float4*)mask)[i4];
        mk[0] = mv.x != 0.f; mk[1] = mv.y != 0.f; mk[2] = mv.z != 0.f; mk[3] = mv.w != 0.f;
    } else {
        int4 mv = ((const int4*)mask)[i4];
        mk[0] = mv.x; mk[1] = mv.y; mk[2] = mv.z; mk[3] = mv.w;
    }
    __nv_bfloat16 h4[4], l4[4];
#pragma unroll
    for (int j = 0; j < 4; j++) {
        float wj = mk[j] ? w[j] : 0.0f;
        h4[j] = __float2bfloat16(wj);
        l4[j] = __float2bfloat16(wj - __bfloat162float(h4[j]));
    }
    ((uint2*)g_Wh)[i4] = *(uint2*)h4;
    ((uint2*)g_Wl)[i4] = *(uint2*)l4;
}

// ===================== HMMA GEMM ===========================================
constexpr int BM = 128;
constexpr int BN = 128;
constexpr int BK = 32;
constexpr int STAGES = 4;

// per-stage: Ah | Al | Bh | Bl, each BM(BN) x BK bf16 = 8KB
constexpr int ARR_BYTES  = 128 * BK * 2;           // 8192
constexpr int OFF_A_H = 0;
constexpr int OFF_A_L = ARR_BYTES;
constexpr int OFF_B_H = 2 * ARR_BYTES;
constexpr int OFF_B_L = 3 * ARR_BYTES;
constexpr int STAGE_BYTES = 4 * ARR_BYTES;          // 32768
constexpr int SMEM_TOTAL = STAGES * STAGE_BYTES;    // 131072

// pair-packed SW128 smem offset for (row, kbyte in [0,64))
__device__ __forceinline__ uint32_t swz(uint32_t r, uint32_t kb) {
    uint32_t off = ((r >> 1) << 7) + ((r & 1) << 6) + kb;
    return off ^ ((off >> 3) & 0x70);
}

__device__ __forceinline__ uint32_t smem_u32(const void* p) {
    uint32_t a;
    asm("{ .reg .u64 t; cvta.to.shared.u64 t, %1; cvt.u32.u64 %0, t; }"
        : "=r"(a) : "l"(p));
    return a;
}
__device__ __forceinline__ void cp_async16(uint32_t saddr, const void* gaddr) {
    asm volatile("cp.async.cg.shared.global [%0], [%1], 16;"
                 :: "r"(saddr), "l"(gaddr));
}
#define CP_COMMIT() asm volatile("cp.async.commit_group;" ::: "memory")
#define CP_WAIT(n)  asm volatile("cp.async.wait_group %0;" :: "n"(n) : "memory")

__device__ __forceinline__ void ldsm_x4(uint32_t* r, uint32_t addr) {
    asm volatile("ldmatrix.sync.aligned.m8n8.x4.shared.b16 {%0,%1,%2,%3}, [%4];"
                 : "=r"(r[0]), "=r"(r[1]), "=r"(r[2]), "=r"(r[3]) : "r"(addr));
}
__device__ __forceinline__ void mma_bf16(float* d, const uint32_t* a,
                                         const uint32_t* b) {
    asm volatile(
        "mma.sync.aligned.m16n8k16.row.col.f32.bf16.bf16.f32 "
        "{%0,%1,%2,%3},{%4,%5,%6,%7},{%8,%9},{%0,%1,%2,%3};"
        : "+f"(d[0]), "+f"(d[1]), "+f"(d[2]), "+f"(d[3])
        : "r"(a[0]), "r"(a[1]), "r"(a[2]), "r"(a[3]), "r"(b[0]), "r"(b[1]));
}

__global__ __launch_bounds__(256, 1)
void gemm_hmma_kernel(const float* __restrict__ bias,
                      float* __restrict__ C,
                      int M, int N, int K) {
    extern __shared__ char smem[];
    const uint32_t sb = smem_u32(smem);
    const int tid  = threadIdx.x;
    const int lane = tid & 31;
    const int wid  = tid >> 5;
    const int warp_m = (wid & 1) * 64;    // 2 warps in M
    const int warp_n = (wid >> 1) * 32;   // 4 warps in N

    const int bm = blockIdx.y * BM;
    const int bn = blockIdx.x * BN;
    const int NK = K / BK;

    // ---- cp.async per-thread mapping (2 x 16B chunks per array) ----
    const int ccc = tid & 3;              // 16B chunk within 64B row
    const int ra  = tid >> 2;             // row 0..63
    const int rb  = ra + 64;              // row 64..127
    const uint32_t so_a = swz(ra, ccc * 16);
    const uint32_t so_b = swz(rb, ccc * 16);
    // element offset within a row block: ccc*8 bf16
    const __nv_bfloat16* gAh = g_Ah + (size_t)(bm + ra) * K + ccc * 8;
    const __nv_bfloat16* gAh2 = g_Ah + (size_t)(bm + rb) * K + ccc * 8;
    const __nv_bfloat16* gAl = g_Al + (size_t)(bm + ra) * K + ccc * 8;
    const __nv_bfloat16* gAl2 = g_Al + (size_t)(bm + rb) * K + ccc * 8;
    const __nv_bfloat16* gBh = g_Wh + (size_t)(bn + ra) * K + ccc * 8;
    const __nv_bfloat16* gBh2 = g_Wh + (size_t)(bn + rb) * K + ccc * 8;
    const __nv_bfloat16* gBl = g_Wl + (size_t)(bn + ra) * K + ccc * 8;
    const __nv_bfloat16* gBl2 = g_Wl + (size_t)(bn + rb) * K + ccc * 8;

    auto load_stage = [&](int kt, int st) {
        const uint32_t s0 = sb + st * STAGE_BYTES;
        const int ko = kt * BK;
        cp_async16(s0 + OFF_A_H + so_a, gAh + ko);
        cp_async16(s0 + OFF_A_H + so_b, gAh2 + ko);
        cp_async16(s0 + OFF_A_L + so_a, gAl + ko);
        cp_async16(s0 + OFF_A_L + so_b, gAl2 + ko);
        cp_async16(s0 + OFF_B_H + so_a, gBh + ko);
        cp_async16(s0 + OFF_B_H + so_b, gBh2 + ko);
        cp_async16(s0 + OFF_B_L + so_a, gBl + ko);
        cp_async16(s0 + OFF_B_L + so_b, gBl2 + ko);
    };

    // ---- ldmatrix per-lane smem offsets (stage-relative) ----
    // A frag (m-tile mi, substep ks): row = warp_m+mi*16+(lane&7)+((lane>>3)&1)*8
    //                                 kb  = ks*32 + ((lane>>4)&1)*16
    const uint32_t rA = warp_m + (lane & 7) + ((lane >> 3) & 1) * 8;
    const uint32_t kbA_hi = ((lane >> 4) & 1) * 16;
    uint32_t offA[4][2];
#pragma unroll
    for (int mi = 0; mi < 4; mi++)
#pragma unroll
        for (int ks = 0; ks < 2; ks++)
            offA[mi][ks] = swz(rA + mi * 16, ks * 32 + kbA_hi);
    // B frag (n-pair q, substep ks): row = warp_n+q*16+(lane&7)+((lane>>4)&1)*8
    //                                kb  = ks*32 + ((lane>>3)&1)*16
    const uint32_t rB = warp_n + (lane & 7) + ((lane >> 4) & 1) * 8;
    const uint32_t kbB_hi = ((lane >> 3) & 1) * 16;
    uint32_t offB[2][2];
#pragma unroll
    for (int q = 0; q < 2; q++)
#pragma unroll
        for (int ks = 0; ks < 2; ks++)
            offB[q][ks] = swz(rB + q * 16, ks * 32 + kbB_hi);

    float acc[4][4][4];
#pragma unroll
    for (int mi = 0; mi < 4; mi++)
#pragma unroll
        for (int ni = 0; ni < 4; ni++)
#pragma unroll
            for (int e = 0; e < 4; e++) acc[mi][ni][e] = 0.0f;

    // ---- prologue: stages 0..2 ----
    load_stage(0, 0); CP_COMMIT();
    load_stage(1, 1); CP_COMMIT();
    load_stage(2, 2); CP_COMMIT();

    for (int kt = 0; kt < NK; kt++) {
        CP_WAIT(2);
        __syncthreads();
        // issue stage kt+3 (overwrites stage read in iter kt-1; barrier passed)
        if (kt + 3 < NK) load_stage(kt + 3, (kt + 3) & 3);
        CP_COMMIT();

        const uint32_t s0 = sb + (kt & 3) * STAGE_BYTES;
#pragma unroll
        for (int ks = 0; ks < 2; ks++) {
            uint32_t ah[4][4], al[4][4], bh[2][4], bl[2][4];
#pragma unroll
            for (int mi = 0; mi < 4; mi++) {
                ldsm_x4(ah[mi], s0 + OFF_A_H + offA[mi][ks]);
                ldsm_x4(al[mi], s0 + OFF_A_L + offA[mi][ks]);
            }
#pragma unroll
            for (int q = 0; q < 2; q++) {
                ldsm_x4(bh[q], s0 + OFF_B_H + offB[q][ks]);
                ldsm_x4(bl[q], s0 + OFF_B_L + offB[q][ks]);
            }
#pragma unroll
            for (int mi = 0; mi < 4; mi++)
#pragma unroll
                for (int ni = 0; ni < 4; ni++) {
                    const int q = ni >> 1, h = (ni & 1) * 2;
                    mma_bf16(acc[mi][ni], ah[mi], &bh[q][h]);   // xh*Wh
                    mma_bf16(acc[mi][ni], al[mi], &bh[q][h]);   // xl*Wh
                    mma_bf16(acc[mi][ni], ah[mi], &bl[q][h]);   // xh*Wl
                }
        }
    }

    // ---- epilogue: + bias, float2 stores ----
#pragma unroll
    for (int mi = 0; mi < 4; mi++) {
        const int r0 = bm + warp_m + mi * 16 + (lane >> 2);
#pragma unroll
        for (int ni = 0; ni < 4; ni++) {
            const int c0 = bn + warp_n + ni * 8 + (lane & 3) * 2;
            const float b0 = bias[c0];
            const float b1 = bias[c0 + 1];
            float2 v0 = make_float2(acc[mi][ni][0] + b0, acc[mi][ni][1] + b1);
            float2 v1 = make_float2(acc[mi][ni][2] + b0, acc[mi][ni][3] + b1);
            *(float2*)(C + (size_t)r0 * N + c0) = v0;
            *(float2*)(C + (size_t)(r0 + 8) * N + c0) = v1;
        }
    }
}

// ===================== launch ==============================================
extern "C" void kernel_launch(void* const* d_in, const int* in_sizes, int n_in,
                              void* d_out, int out_size) {
    const float* x      = (const float*)d_in[0];
    const int*   Wq     = (const int*)d_in[1];
    const float* scales = (const float*)d_in[2];
    const float* zeros  = (const float*)d_in[3];
    const void*  mask   = d_in[4];
    const float* scale2 = (const float*)d_in[5];
    const float* bias   = (const float*)d_in[6];
    float* out = (float*)d_out;

    const int I = in_sizes[5];
    const int O = in_sizes[6];
    const int M = in_sizes[0] / I;
    const int ngroups = in_sizes[2] / O;
    const int G = I / ngroups;

    int nwords = O * I / 4;
    if (nwords > 16384) nwords = 16384;
    detect_mask_kernel<<<1, 1024>>>((const unsigned*)mask, nwords);

    int total4 = M * I / 4;
    split_x_kernel<<<(total4 + 255) / 256, 256>>>(x, total4);

    int totalW4 = O * I / 4;
    dequant_split_kernel<<<(totalW4 + 255) / 256, 256>>>(Wq, scales, zeros,
                                                         mask, scale2, O, I, G);

    cudaFuncSetAttribute(gemm_hmma_kernel,
                         cudaFuncAttributeMaxDynamicSharedMemorySize, SMEM_TOTAL);
    dim3 grid(O / BN, M / BM);
    gemm_hmma_kernel<<<grid, 256, SMEM_TOTAL>>>(bias, out, M, O, I);
}

// round 5
// speedup vs baseline: 4.3326x; 1.4658x over previous
#include <cuda_runtime.h>
#include <cuda_fp16.h>
#include <cuda_bf16.h>
#include <cstdint>

// ---------------------------------------------------------------------------
// SparseQuantLinear: out = x @ W^T + bias, W = mask?(Wq-z)*s*s2:0
// M=16384, N=4096, K=4096.
// R5: fp16 2-term split GEMM on mma.sync.m16n8k16.f32.f16.f16.f32:
//   x = xh + xl (fp16 pair, exact to 2^-22), W -> fp16 once.
//   out = xh*Wh + xl*Wh (+bias); dropped x*Wl ~ 2^-11 -> rel_err ~3e-4.
// BM=128,BN=128,BK=32, 4-stage cp.async pipeline, 24KB/stage, occupancy 2.
// ---------------------------------------------------------------------------

#define MAX_M 16384u
#define MAX_K 4096u
#define MAX_O 4096u

__device__ __half g_Ah[(size_t)MAX_M * MAX_K];
__device__ __half g_Al[(size_t)MAX_M * MAX_K];
__device__ __half g_Wh[(size_t)MAX_O * MAX_K];
__device__ int g_mask_mode;   // 0 int32 / 1 byte / 2 float mask

// ===================== prep kernels ========================================
__global__ void detect_mask_kernel(const unsigned* __restrict__ m, int nwords) {
    __shared__ int s_mode;
    if (threadIdx.x == 0) s_mode = 0;
    __syncthreads();
    int mode = 0;
    for (int i = threadIdx.x; i < nwords; i += blockDim.x) {
        unsigned v = m[i];
        if (v == 0x3F800000u) { if (mode < 2) mode = 2; }
        else if (v > 1u)      { if (mode < 1) mode = 1; }
    }
    if (mode) atomicMax(&s_mode, mode);
    __syncthreads();
    if (threadIdx.x == 0) g_mask_mode = s_mode;
}

__global__ void split_x_kernel(const float* __restrict__ x, int total4) {
    int i = blockIdx.x * blockDim.x + threadIdx.x;
    if (i >= total4) return;
    float4 v = ((const float4*)x)[i];
    float vv[4] = {v.x, v.y, v.z, v.w};
    __half h4[4], l4[4];
#pragma unroll
    for (int j = 0; j < 4; j++) {
        h4[j] = __float2half(vv[j]);
        l4[j] = __float2half(vv[j] - __half2float(h4[j]));
    }
    ((uint2*)g_Ah)[i] = *(uint2*)h4;
    ((uint2*)g_Al)[i] = *(uint2*)l4;
}

__global__ void dequant_kernel(const int* __restrict__ Wq,
                               const float* __restrict__ scales,
                               const float* __restrict__ zeros,
                               const void* __restrict__ mask,
                               const float* __restrict__ scale2,
                               int O, int I, int G) {
    int i4 = blockIdx.x * blockDim.x + threadIdx.x;     // 4 elems / thread
    int total4 = O * I / 4;
    if (i4 >= total4) return;
    int idx0 = i4 * 4;
    int n = idx0 / I;
    int k0 = idx0 - n * I;
    int gi = n * (I / G) + k0 / G;                      // G>=4 -> same group
    float z = zeros[gi], s = scales[gi];
    int4 q = ((const int4*)Wq)[i4];
    float4 s2 = *(const float4*)(scale2 + k0);
    int mode = g_mask_mode;
    float w[4];
    w[0] = ((float)q.x - z) * s * s2.x;
    w[1] = ((float)q.y - z) * s * s2.y;
    w[2] = ((float)q.z - z) * s * s2.z;
    w[3] = ((float)q.w - z) * s * s2.w;
    bool mk[4];
    if (mode == 1) {
        const unsigned char* mp = (const unsigned char*)mask + idx0;
        mk[0] = mp[0]; mk[1] = mp[1]; mk[2] = mp[2]; mk[3] = mp[3];
    } else if (mode == 2) {
        float4 mv = ((const float4*)mask)[i4];
        mk[0] = mv.x != 0.f; mk[1] = mv.y != 0.f; mk[2] = mv.z != 0.f; mk[3] = mv.w != 0.f;
    } else {
        int4 mv = ((const int4*)mask)[i4];
        mk[0] = mv.x; mk[1] = mv.y; mk[2] = mv.z; mk[3] = mv.w;
    }
    __half h4[4];
#pragma unroll
    for (int j = 0; j < 4; j++)
        h4[j] = __float2half(mk[j] ? w[j] : 0.0f);
    ((uint2*)g_Wh)[i4] = *(uint2*)h4;
}

// ===================== HMMA GEMM ===========================================
constexpr int BM = 128;
constexpr int BN = 128;
constexpr int BK = 32;
constexpr int STAGES = 4;

constexpr int ARR_BYTES  = 128 * BK * 2;            // 8192
constexpr int OFF_A_H = 0;
constexpr int OFF_A_L = ARR_BYTES;
constexpr int OFF_B_H = 2 * ARR_BYTES;
constexpr int STAGE_BYTES = 3 * ARR_BYTES;          // 24576
constexpr int SMEM_TOTAL = STAGES * STAGE_BYTES;    // 98304

// pair-packed SW128 smem offset for (row, kbyte in [0,64))
__device__ __forceinline__ uint32_t swz(uint32_t r, uint32_t kb) {
    uint32_t off = ((r >> 1) << 7) + ((r & 1) << 6) + kb;
    return off ^ ((off >> 3) & 0x70);
}

__device__ __forceinline__ uint32_t smem_u32(const void* p) {
    uint32_t a;
    asm("{ .reg .u64 t; cvta.to.shared.u64 t, %1; cvt.u32.u64 %0, t; }"
        : "=r"(a) : "l"(p));
    return a;
}
__device__ __forceinline__ void cp_async16(uint32_t saddr, const void* gaddr) {
    asm volatile("cp.async.cg.shared.global [%0], [%1], 16;"
                 :: "r"(saddr), "l"(gaddr));
}
#define CP_COMMIT() asm volatile("cp.async.commit_group;" ::: "memory")
#define CP_WAIT(n)  asm volatile("cp.async.wait_group %0;" :: "n"(n) : "memory")

__device__ __forceinline__ void ldsm_x4(uint32_t* r, uint32_t addr) {
    asm volatile("ldmatrix.sync.aligned.m8n8.x4.shared.b16 {%0,%1,%2,%3}, [%4];"
                 : "=r"(r[0]), "=r"(r[1]), "=r"(r[2]), "=r"(r[3]) : "r"(addr));
}
__device__ __forceinline__ void mma_f16(float* d, const uint32_t* a,
                                        const uint32_t* b) {
    asm volatile(
        "mma.sync.aligned.m16n8k16.row.col.f32.f16.f16.f32 "
        "{%0,%1,%2,%3},{%4,%5,%6,%7},{%8,%9},{%0,%1,%2,%3};"
        : "+f"(d[0]), "+f"(d[1]), "+f"(d[2]), "+f"(d[3])
        : "r"(a[0]), "r"(a[1]), "r"(a[2]), "r"(a[3]), "r"(b[0]), "r"(b[1]));
}

__global__ __launch_bounds__(256, 2)
void gemm_hmma_kernel(const float* __restrict__ bias,
                      float* __restrict__ C,
                      int M, int N, int K) {
    extern __shared__ char smem[];
    const uint32_t sb = smem_u32(smem);
    const int tid  = threadIdx.x;
    const int lane = tid & 31;
    const int wid  = tid >> 5;
    const int warp_m = (wid & 1) * 64;    // 2 warps in M
    const int warp_n = (wid >> 1) * 32;   // 4 warps in N

    const int bm = blockIdx.y * BM;
    const int bn = blockIdx.x * BN;
    const int NK = K / BK;

    // ---- cp.async mapping: per array, 2 x 16B per thread ----
    const int ccc = tid & 3;
    const int ra  = tid >> 2;             // 0..63
    const int rb  = ra + 64;
    const uint32_t so_a = swz(ra, ccc * 16);
    const uint32_t so_b = swz(rb, ccc * 16);
    const __half* gAh  = g_Ah + (size_t)(bm + ra) * K + ccc * 8;
    const __half* gAh2 = g_Ah + (size_t)(bm + rb) * K + ccc * 8;
    const __half* gAl  = g_Al + (size_t)(bm + ra) * K + ccc * 8;
    const __half* gAl2 = g_Al + (size_t)(bm + rb) * K + ccc * 8;
    const __half* gBh  = g_Wh + (size_t)(bn + ra) * K + ccc * 8;
    const __half* gBh2 = g_Wh + (size_t)(bn + rb) * K + ccc * 8;

    auto load_stage = [&](int kt, int st) {
        const uint32_t s0 = sb + st * STAGE_BYTES;
        const int ko = kt * BK;
        cp_async16(s0 + OFF_A_H + so_a, gAh + ko);
        cp_async16(s0 + OFF_A_H + so_b, gAh2 + ko);
        cp_async16(s0 + OFF_A_L + so_a, gAl + ko);
        cp_async16(s0 + OFF_A_L + so_b, gAl2 + ko);
        cp_async16(s0 + OFF_B_H + so_a, gBh + ko);
        cp_async16(s0 + OFF_B_H + so_b, gBh2 + ko);
    };

    // ---- ldmatrix lane offsets ----
    const uint32_t rA = warp_m + (lane & 7) + ((lane >> 3) & 1) * 8;
    const uint32_t kbA_hi = ((lane >> 4) & 1) * 16;
    uint32_t offA[4][2];
#pragma unroll
    for (int mi = 0; mi < 4; mi++)
#pragma unroll
        for (int ks = 0; ks < 2; ks++)
            offA[mi][ks] = swz(rA + mi * 16, ks * 32 + kbA_hi);
    const uint32_t rB = warp_n + (lane & 7) + ((lane >> 4) & 1) * 8;
    const uint32_t kbB_hi = ((lane >> 3) & 1) * 16;
    uint32_t offB[2][2];
#pragma unroll
    for (int q = 0; q < 2; q++)
#pragma unroll
        for (int ks = 0; ks < 2; ks++)
            offB[q][ks] = swz(rB + q * 16, ks * 32 + kbB_hi);

    float acc[4][4][4];
#pragma unroll
    for (int mi = 0; mi < 4; mi++)
#pragma unroll
        for (int ni = 0; ni < 4; ni++)
#pragma unroll
            for (int e = 0; e < 4; e++) acc[mi][ni][e] = 0.0f;

    load_stage(0, 0); CP_COMMIT();
    load_stage(1, 1); CP_COMMIT();
    load_stage(2, 2); CP_COMMIT();

    for (int kt = 0; kt < NK; kt++) {
        CP_WAIT(2);
        __syncthreads();
        if (kt + 3 < NK) load_stage(kt + 3, (kt + 3) & 3);
        CP_COMMIT();

        const uint32_t s0 = sb + (kt & 3) * STAGE_BYTES;
#pragma unroll
        for (int ks = 0; ks < 2; ks++) {
            uint32_t ah[4][4], al[4][4], bh[2][4];
#pragma unroll
            for (int q = 0; q < 2; q++)
                ldsm_x4(bh[q], s0 + OFF_B_H + offB[q][ks]);
#pragma unroll
            for (int mi = 0; mi < 4; mi++) {
                ldsm_x4(ah[mi], s0 + OFF_A_H + offA[mi][ks]);
                ldsm_x4(al[mi], s0 + OFF_A_L + offA[mi][ks]);
            }
#pragma unroll
            for (int mi = 0; mi < 4; mi++)
#pragma unroll
                for (int ni = 0; ni < 4; ni++) {
                    const int q = ni >> 1, h = (ni & 1) * 2;
                    mma_f16(acc[mi][ni], ah[mi], &bh[q][h]);   // xh*Wh
                    mma_f16(acc[mi][ni], al[mi], &bh[q][h]);   // xl*Wh
                }
        }
    }

    // ---- epilogue: + bias ----
#pragma unroll
    for (int mi = 0; mi < 4; mi++) {
        const int r0 = bm + warp_m + mi * 16 + (lane >> 2);
#pragma unroll
        for (int ni = 0; ni < 4; ni++) {
            const int c0 = bn + warp_n + ni * 8 + (lane & 3) * 2;
            const float b0 = bias[c0];
            const float b1 = bias[c0 + 1];
            float2 v0 = make_float2(acc[mi][ni][0] + b0, acc[mi][ni][1] + b1);
            float2 v1 = make_float2(acc[mi][ni][2] + b0, acc[mi][ni][3] + b1);
            *(float2*)(C + (size_t)r0 * N + c0) = v0;
            *(float2*)(C + (size_t)(r0 + 8) * N + c0) = v1;
        }
    }
}

// ===================== launch ==============================================
extern "C" void kernel_launch(void* const* d_in, const int* in_sizes, int n_in,
                              void* d_out, int out_size) {
    const float* x      = (const float*)d_in[0];
    const int*   Wq     = (const int*)d_in[1];
    const float* scales = (const float*)d_in[2];
    const float* zeros  = (const float*)d_in[3];
    const void*  mask   = d_in[4];
    const float* scale2 = (const float*)d_in[5];
    const float* bias   = (const float*)d_in[6];
    float* out = (float*)d_out;

    const int I = in_sizes[5];
    const int O = in_sizes[6];
    const int M = in_sizes[0] / I;
    const int ngroups = in_sizes[2] / O;
    const int G = I / ngroups;

    int nwords = O * I / 4;
    if (nwords > 16384) nwords = 16384;
    detect_mask_kernel<<<1, 1024>>>((const unsigned*)mask, nwords);

    int total4 = M * I / 4;
    split_x_kernel<<<(total4 + 255) / 256, 256>>>(x, total4);

    int totalW4 = O * I / 4;
    dequant_kernel<<<(totalW4 + 255) / 256, 256>>>(Wq, scales, zeros,
                                                   mask, scale2, O, I, G);

    cudaFuncSetAttribute(gemm_hmma_kernel,
                         cudaFuncAttributeMaxDynamicSharedMemorySize, SMEM_TOTAL);
    dim3 grid(O / BN, M / BM);
    gemm_hmma_kernel<<<grid, 256, SMEM_TOTAL>>>(bias, out, M, O, I);
}

// round 6
// speedup vs baseline: 7.7259x; 1.7832x over previous
#include <cuda_runtime.h>
#include <cuda_fp16.h>
#include <cstdint>

// ---------------------------------------------------------------------------
// SparseQuantLinear: out = x @ W^T + bias, W = mask?(Wq-z)*s*s2:0
// M=16384, N=4096, K=4096.
// R6: single-term fp16 GEMM on mma.sync.m16n8k16.f32.f16.f16.f32:
//   A = fp16(x), B = fp16(W), fp32 accumulate.
//   Dropped terms x*Wl and xl*W are independent ~2^-11 relative errors;
//   calibrated from R5: predicted rel_err ~3e-4 < 1e-3.
// BM=128,BN=128,BK=32, 6-stage cp.async pipeline (16KB/stage), occupancy 2.
// ---------------------------------------------------------------------------

#define MAX_M 16384u
#define MAX_K 4096u
#define MAX_O 4096u

__device__ __half g_Ah[(size_t)MAX_M * MAX_K];
__device__ __half g_Wh[(size_t)MAX_O * MAX_K];
__device__ int g_mask_mode;   // 0 int32 / 1 byte / 2 float mask

// ===================== prep kernels ========================================
__global__ void detect_mask_kernel(const unsigned* __restrict__ m, int nwords) {
    __shared__ int s_mode;
    if (threadIdx.x == 0) s_mode = 0;
    __syncthreads();
    int mode = 0;
    for (int i = threadIdx.x; i < nwords; i += blockDim.x) {
        unsigned v = m[i];
        if (v == 0x3F800000u) { if (mode < 2) mode = 2; }
        else if (v > 1u)      { if (mode < 1) mode = 1; }
    }
    if (mode) atomicMax(&s_mode, mode);
    __syncthreads();
    if (threadIdx.x == 0) g_mask_mode = s_mode;
}

__global__ void cvt_x_kernel(const float* __restrict__ x, int total4) {
    int i = blockIdx.x * blockDim.x + threadIdx.x;
    if (i >= total4) return;
    float4 v = ((const float4*)x)[i];
    __half h4[4];
    h4[0] = __float2half(v.x);
    h4[1] = __float2half(v.y);
    h4[2] = __float2half(v.z);
    h4[3] = __float2half(v.w);
    ((uint2*)g_Ah)[i] = *(uint2*)h4;
}

__global__ void dequant_kernel(const int* __restrict__ Wq,
                               const float* __restrict__ scales,
                               const float* __restrict__ zeros,
                               const void* __restrict__ mask,
                               const float* __restrict__ scale2,
                               int O, int I, int G) {
    int i4 = blockIdx.x * blockDim.x + threadIdx.x;     // 4 elems / thread
    int total4 = O * I / 4;
    if (i4 >= total4) return;
    int idx0 = i4 * 4;
    int n = idx0 / I;
    int k0 = idx0 - n * I;
    int gi = n * (I / G) + k0 / G;                      // G>=4 -> same group
    float z = zeros[gi], s = scales[gi];
    int4 q = ((const int4*)Wq)[i4];
    float4 s2 = *(const float4*)(scale2 + k0);
    int mode = g_mask_mode;
    float w[4];
    w[0] = ((float)q.x - z) * s * s2.x;
    w[1] = ((float)q.y - z) * s * s2.y;
    w[2] = ((float)q.z - z) * s * s2.z;
    w[3] = ((float)q.w - z) * s * s2.w;
    bool mk[4];
    if (mode == 1) {
        const unsigned char* mp = (const unsigned char*)mask + idx0;
        mk[0] = mp[0]; mk[1] = mp[1]; mk[2] = mp[2]; mk[3] = mp[3];
    } else if (mode == 2) {
        float4 mv = ((const float4*)mask)[i4];
        mk[0] = mv.x != 0.f; mk[1] = mv.y != 0.f; mk[2] = mv.z != 0.f; mk[3] = mv.w != 0.f;
    } else {
        int4 mv = ((const int4*)mask)[i4];
        mk[0] = mv.x; mk[1] = mv.y; mk[2] = mv.z; mk[3] = mv.w;
    }
    __half h4[4];
#pragma unroll
    for (int j = 0; j < 4; j++)
        h4[j] = __float2half(mk[j] ? w[j] : 0.0f);
    ((uint2*)g_Wh)[i4] = *(uint2*)h4;
}

// ===================== HMMA GEMM ===========================================
constexpr int BM = 128;
constexpr int BN = 128;
constexpr int BK = 32;
constexpr int STAGES = 6;

constexpr int ARR_BYTES  = 128 * BK * 2;            // 8192
constexpr int OFF_A = 0;
constexpr int OFF_B = ARR_BYTES;
constexpr int STAGE_BYTES = 2 * ARR_BYTES;          // 16384
constexpr int SMEM_TOTAL = STAGES * STAGE_BYTES;    // 98304

// pair-packed SW128 smem offset for (row, kbyte in [0,64))
__device__ __forceinline__ uint32_t swz(uint32_t r, uint32_t kb) {
    uint32_t off = ((r >> 1) << 7) + ((r & 1) << 6) + kb;
    return off ^ ((off >> 3) & 0x70);
}

__device__ __forceinline__ uint32_t smem_u32(const void* p) {
    uint32_t a;
    asm("{ .reg .u64 t; cvta.to.shared.u64 t, %1; cvt.u32.u64 %0, t; }"
        : "=r"(a) : "l"(p));
    return a;
}
__device__ __forceinline__ void cp_async16(uint32_t saddr, const void* gaddr) {
    asm volatile("cp.async.cg.shared.global [%0], [%1], 16;"
                 :: "r"(saddr), "l"(gaddr));
}
#define CP_COMMIT() asm volatile("cp.async.commit_group;" ::: "memory")
#define CP_WAIT(n)  asm volatile("cp.async.wait_group %0;" :: "n"(n) : "memory")

__device__ __forceinline__ void ldsm_x4(uint32_t* r, uint32_t addr) {
    asm volatile("ldmatrix.sync.aligned.m8n8.x4.shared.b16 {%0,%1,%2,%3}, [%4];"
                 : "=r"(r[0]), "=r"(r[1]), "=r"(r[2]), "=r"(r[3]) : "r"(addr));
}
__device__ __forceinline__ void mma_f16(float* d, const uint32_t* a,
                                        const uint32_t* b) {
    asm volatile(
        "mma.sync.aligned.m16n8k16.row.col.f32.f16.f16.f32 "
        "{%0,%1,%2,%3},{%4,%5,%6,%7},{%8,%9},{%0,%1,%2,%3};"
        : "+f"(d[0]), "+f"(d[1]), "+f"(d[2]), "+f"(d[3])
        : "r"(a[0]), "r"(a[1]), "r"(a[2]), "r"(a[3]), "r"(b[0]), "r"(b[1]));
}

__global__ __launch_bounds__(256, 2)
void gemm_hmma_kernel(const float* __restrict__ bias,
                      float* __restrict__ C,
                      int M, int N, int K) {
    extern __shared__ char smem[];
    const uint32_t sb = smem_u32(smem);
    const int tid  = threadIdx.x;
    const int lane = tid & 31;
    const int wid  = tid >> 5;
    const int warp_m = (wid & 1) * 64;    // 2 warps in M
    const int warp_n = (wid >> 1) * 32;   // 4 warps in N

    const int bm = blockIdx.y * BM;
    const int bn = blockIdx.x * BN;
    const int NK = K / BK;

    // ---- cp.async mapping: per array, 2 x 16B per thread ----
    const int ccc = tid & 3;
    const int ra  = tid >> 2;             // 0..63
    const int rb  = ra + 64;
    const uint32_t so_a = swz(ra, ccc * 16);
    const uint32_t so_b = swz(rb, ccc * 16);
    const __half* gA  = g_Ah + (size_t)(bm + ra) * K + ccc * 8;
    const __half* gA2 = g_Ah + (size_t)(bm + rb) * K + ccc * 8;
    const __half* gB  = g_Wh + (size_t)(bn + ra) * K + ccc * 8;
    const __half* gB2 = g_Wh + (size_t)(bn + rb) * K + ccc * 8;

    auto load_stage = [&](int kt, int st) {
        const uint32_t s0 = sb + st * STAGE_BYTES;
        const int ko = kt * BK;
        cp_async16(s0 + OFF_A + so_a, gA + ko);
        cp_async16(s0 + OFF_A + so_b, gA2 + ko);
        cp_async16(s0 + OFF_B + so_a, gB + ko);
        cp_async16(s0 + OFF_B + so_b, gB2 + ko);
    };

    // ---- ldmatrix lane offsets ----
    const uint32_t rA = warp_m + (lane & 7) + ((lane >> 3) & 1) * 8;
    const uint32_t kbA_hi = ((lane >> 4) & 1) * 16;
    uint32_t offA[4][2];
#pragma unroll
    for (int mi = 0; mi < 4; mi++)
#pragma unroll
        for (int ks = 0; ks < 2; ks++)
            offA[mi][ks] = swz(rA + mi * 16, ks * 32 + kbA_hi);
    const uint32_t rB = warp_n + (lane & 7) + ((lane >> 4) & 1) * 8;
    const uint32_t kbB_hi = ((lane >> 3) & 1) * 16;
    uint32_t offB[2][2];
#pragma unroll
    for (int q = 0; q < 2; q++)
#pragma unroll
        for (int ks = 0; ks < 2; ks++)
            offB[q][ks] = swz(rB + q * 16, ks * 32 + kbB_hi);

    float acc[4][4][4];
#pragma unroll
    for (int mi = 0; mi < 4; mi++)
#pragma unroll
        for (int ni = 0; ni < 4; ni++)
#pragma unroll
            for (int e = 0; e < 4; e++) acc[mi][ni][e] = 0.0f;

    // prologue: 5 stages in flight
#pragma unroll
    for (int p = 0; p < 5; p++) {
        load_stage(p, p);
        CP_COMMIT();
    }

    for (int kt = 0; kt < NK; kt++) {
        CP_WAIT(4);
        __syncthreads();
        if (kt + 5 < NK) load_stage(kt + 5, (kt + 5) % STAGES);
        CP_COMMIT();

        const uint32_t s0 = sb + (kt % STAGES) * STAGE_BYTES;
#pragma unroll
        for (int ks = 0; ks < 2; ks++) {
            uint32_t ah[4][4], bh[2][4];
#pragma unroll
            for (int q = 0; q < 2; q++)
                ldsm_x4(bh[q], s0 + OFF_B + offB[q][ks]);
#pragma unroll
            for (int mi = 0; mi < 4; mi++)
                ldsm_x4(ah[mi], s0 + OFF_A + offA[mi][ks]);
#pragma unroll
            for (int mi = 0; mi < 4; mi++)
#pragma unroll
                for (int ni = 0; ni < 4; ni++) {
                    const int q = ni >> 1, h = (ni & 1) * 2;
                    mma_f16(acc[mi][ni], ah[mi], &bh[q][h]);
                }
        }
    }

    // ---- epilogue: + bias ----
#pragma unroll
    for (int mi = 0; mi < 4; mi++) {
        const int r0 = bm + warp_m + mi * 16 + (lane >> 2);
#pragma unroll
        for (int ni = 0; ni < 4; ni++) {
            const int c0 = bn + warp_n + ni * 8 + (lane & 3) * 2;
            const float b0 = bias[c0];
            const float b1 = bias[c0 + 1];
            float2 v0 = make_float2(acc[mi][ni][0] + b0, acc[mi][ni][1] + b1);
            float2 v1 = make_float2(acc[mi][ni][2] + b0, acc[mi][ni][3] + b1);
            *(float2*)(C + (size_t)r0 * N + c0) = v0;
            *(float2*)(C + (size_t)(r0 + 8) * N + c0) = v1;
        }
    }
}

// ===================== launch ==============================================
extern "C" void kernel_launch(void* const* d_in, const int* in_sizes, int n_in,
                              void* d_out, int out_size) {
    const float* x      = (const float*)d_in[0];
    const int*   Wq     = (const int*)d_in[1];
    const float* scales = (const float*)d_in[2];
    const float* zeros  = (const float*)d_in[3];
    const void*  mask   = d_in[4];
    const float* scale2 = (const float*)d_in[5];
    const float* bias   = (const float*)d_in[6];
    float* out = (float*)d_out;

    const int I = in_sizes[5];
    const int O = in_sizes[6];
    const int M = in_sizes[0] / I;
    const int ngroups = in_sizes[2] / O;
    const int G = I / ngroups;

    int nwords = O * I / 4;
    if (nwords > 16384) nwords = 16384;
    detect_mask_kernel<<<1, 1024>>>((const unsigned*)mask, nwords);

    int total4 = M * I / 4;
    cvt_x_kernel<<<(total4 + 255) / 256, 256>>>(x, total4);

    int totalW4 = O * I / 4;
    dequant_kernel<<<(totalW4 + 255) / 256, 256>>>(Wq, scales, zeros,
                                                   mask, scale2, O, I, G);

    cudaFuncSetAttribute(gemm_hmma_kernel,
                         cudaFuncAttributeMaxDynamicSharedMemorySize, SMEM_TOTAL);
    dim3 grid(O / BN, M / BM);
    gemm_hmma_kernel<<<grid, 256, SMEM_TOTAL>>>(bias, out, M, O, I);
}

// round 7
// speedup vs baseline: 8.5237x; 1.1033x over previous
#include <cuda_runtime.h>
#include <cuda_fp16.h>
#include <cstdint>

// ---------------------------------------------------------------------------
// SparseQuantLinear: out = x @ W^T + bias, W = mask?(Wq-z)*s*s2:0
// M=16384, N=4096, K=4096.
// R7: single-term fp16 HMMA GEMM; BK 32->64 (half the barriers),
// 3-stage cp.async pipeline (32KB/stage), occupancy 2.
// ---------------------------------------------------------------------------

#define MAX_M 16384u
#define MAX_K 4096u
#define MAX_O 4096u

__device__ __half g_Ah[(size_t)MAX_M * MAX_K];
__device__ __half g_Wh[(size_t)MAX_O * MAX_K];
__device__ int g_mask_mode;   // 0 int32 / 1 byte / 2 float mask

// ===================== prep kernels ========================================
__global__ void detect_mask_kernel(const unsigned* __restrict__ m, int nwords) {
    __shared__ int s_mode;
    if (threadIdx.x == 0) s_mode = 0;
    __syncthreads();
    int mode = 0;
    for (int i = threadIdx.x; i < nwords; i += blockDim.x) {
        unsigned v = m[i];
        if (v == 0x3F800000u) { if (mode < 2) mode = 2; }
        else if (v > 1u)      { if (mode < 1) mode = 1; }
    }
    if (mode) atomicMax(&s_mode, mode);
    __syncthreads();
    if (threadIdx.x == 0) g_mask_mode = s_mode;
}

__global__ void cvt_x_kernel(const float* __restrict__ x, int total4) {
    int i = blockIdx.x * blockDim.x + threadIdx.x;
    if (i >= total4) return;
    float4 v = ((const float4*)x)[i];
    __half h4[4];
    h4[0] = __float2half(v.x);
    h4[1] = __float2half(v.y);
    h4[2] = __float2half(v.z);
    h4[3] = __float2half(v.w);
    ((uint2*)g_Ah)[i] = *(uint2*)h4;
}

__global__ void dequant_kernel(const int* __restrict__ Wq,
                               const float* __restrict__ scales,
                               const float* __restrict__ zeros,
                               const void* __restrict__ mask,
                               const float* __restrict__ scale2,
                               int O, int I, int G) {
    int i4 = blockIdx.x * blockDim.x + threadIdx.x;     // 4 elems / thread
    int total4 = O * I / 4;
    if (i4 >= total4) return;
    int idx0 = i4 * 4;
    int n = idx0 / I;
    int k0 = idx0 - n * I;
    int gi = n * (I / G) + k0 / G;                      // G>=4 -> same group
    float z = zeros[gi], s = scales[gi];
    int4 q = ((const int4*)Wq)[i4];
    float4 s2 = *(const float4*)(scale2 + k0);
    int mode = g_mask_mode;
    float w[4];
    w[0] = ((float)q.x - z) * s * s2.x;
    w[1] = ((float)q.y - z) * s * s2.y;
    w[2] = ((float)q.z - z) * s * s2.z;
    w[3] = ((float)q.w - z) * s * s2.w;
    bool mk[4];
    if (mode == 1) {
        const unsigned char* mp = (const unsigned char*)mask + idx0;
        mk[0] = mp[0]; mk[1] = mp[1]; mk[2] = mp[2]; mk[3] = mp[3];
    } else if (mode == 2) {
        float4 mv = ((const float4*)mask)[i4];
        mk[0] = mv.x != 0.f; mk[1] = mv.y != 0.f; mk[2] = mv.z != 0.f; mk[3] = mv.w != 0.f;
    } else {
        int4 mv = ((const int4*)mask)[i4];
        mk[0] = mv.x; mk[1] = mv.y; mk[2] = mv.z; mk[3] = mv.w;
    }
    __half h4[4];
#pragma unroll
    for (int j = 0; j < 4; j++)
        h4[j] = __float2half(mk[j] ? w[j] : 0.0f);
    ((uint2*)g_Wh)[i4] = *(uint2*)h4;
}

// ===================== HMMA GEMM ===========================================
constexpr int BM = 128;
constexpr int BN = 128;
constexpr int BK = 64;                               // 128B rows (SW128 atom)
constexpr int STAGES = 3;

constexpr int ARR_BYTES  = 128 * BK * 2;             // 16384
constexpr int OFF_A = 0;
constexpr int OFF_B = ARR_BYTES;
constexpr int STAGE_BYTES = 2 * ARR_BYTES;           // 32768
constexpr int SMEM_TOTAL = STAGES * STAGE_BYTES;     // 98304

// SW128 swizzle for 128B rows: off = r*128 + kb, XOR bits[6:4] with r&7
__device__ __forceinline__ uint32_t swz(uint32_t r, uint32_t kb) {
    return r * 128u + (kb ^ ((r & 7u) << 4));
}

__device__ __forceinline__ uint32_t smem_u32(const void* p) {
    uint32_t a;
    asm("{ .reg .u64 t; cvta.to.shared.u64 t, %1; cvt.u32.u64 %0, t; }"
        : "=r"(a) : "l"(p));
    return a;
}
__device__ __forceinline__ void cp_async16(uint32_t saddr, const void* gaddr) {
    asm volatile("cp.async.cg.shared.global [%0], [%1], 16;"
                 :: "r"(saddr), "l"(gaddr));
}
#define CP_COMMIT() asm volatile("cp.async.commit_group;" ::: "memory")
#define CP_WAIT(n)  asm volatile("cp.async.wait_group %0;" :: "n"(n) : "memory")

__device__ __forceinline__ void ldsm_x4(uint32_t* r, uint32_t addr) {
    asm volatile("ldmatrix.sync.aligned.m8n8.x4.shared.b16 {%0,%1,%2,%3}, [%4];"
                 : "=r"(r[0]), "=r"(r[1]), "=r"(r[2]), "=r"(r[3]) : "r"(addr));
}
__device__ __forceinline__ void mma_f16(float* d, const uint32_t* a,
                                        const uint32_t* b) {
    asm volatile(
        "mma.sync.aligned.m16n8k16.row.col.f32.f16.f16.f32 "
        "{%0,%1,%2,%3},{%4,%5,%6,%7},{%8,%9},{%0,%1,%2,%3};"
        : "+f"(d[0]), "+f"(d[1]), "+f"(d[2]), "+f"(d[3])
        : "r"(a[0]), "r"(a[1]), "r"(a[2]), "r"(a[3]), "r"(b[0]), "r"(b[1]));
}

__global__ __launch_bounds__(256, 2)
void gemm_hmma_kernel(const float* __restrict__ bias,
                      float* __restrict__ C,
                      int M, int N, int K) {
    extern __shared__ char smem[];
    const uint32_t sb = smem_u32(smem);
    const int tid  = threadIdx.x;
    const int lane = tid & 31;
    const int wid  = tid >> 5;
    const int warp_m = (wid & 1) * 64;    // 2 warps in M
    const int warp_n = (wid >> 1) * 32;   // 4 warps in N

    const int bm = blockIdx.y * BM;
    const int bn = blockIdx.x * BN;
    const int NK = K / BK;                // 64

    // ---- cp.async mapping: 128 rows x 8 chunks(16B) per array ----
    // 256 threads: 4 iterations per array. chunk c = tid + i*256:
    //   row = c>>3 (0..127), kc = c&7
    const int kc  = tid & 7;
    const int r0_ = tid >> 3;             // 0..31, +32 per iteration
    uint32_t so[4];
#pragma unroll
    for (int i = 0; i < 4; i++) so[i] = swz(r0_ + i * 32, kc * 16);

    const __half* gA = g_Ah + (size_t)(bm + r0_) * K + kc * 8;
    const __half* gB = g_Wh + (size_t)(bn + r0_) * K + kc * 8;
    const size_t rowstep = (size_t)32 * K;

    auto load_stage = [&](int kt, int st) {
        const uint32_t s0 = sb + st * STAGE_BYTES;
        const int ko = kt * BK;
#pragma unroll
        for (int i = 0; i < 4; i++)
            cp_async16(s0 + OFF_A + so[i], gA + i * rowstep + ko);
#pragma unroll
        for (int i = 0; i < 4; i++)
            cp_async16(s0 + OFF_B + so[i], gB + i * rowstep + ko);
    };

    // ---- ldmatrix lane base offsets (ks folded in via XOR ks<<5) ----
    const uint32_t rA = warp_m + (lane & 7) + ((lane >> 3) & 1) * 8;
    const uint32_t kbA = ((lane >> 4) & 1) * 16;
    uint32_t offA[4];
#pragma unroll
    for (int mi = 0; mi < 4; mi++) offA[mi] = swz(rA + mi * 16, kbA);
    const uint32_t rB = warp_n + (lane & 7) + ((lane >> 4) & 1) * 8;
    const uint32_t kbB = ((lane >> 3) & 1) * 16;
    uint32_t offB[2];
#pragma unroll
    for (int q = 0; q < 2; q++) offB[q] = swz(rB + q * 16, kbB);

    float acc[4][4][4];
#pragma unroll
    for (int mi = 0; mi < 4; mi++)
#pragma unroll
        for (int ni = 0; ni < 4; ni++)
#pragma unroll
            for (int e = 0; e < 4; e++) acc[mi][ni][e] = 0.0f;

    // prologue: 2 stages in flight
    load_stage(0, 0); CP_COMMIT();
    load_stage(1, 1); CP_COMMIT();

    int slot = 0, nslot = 2;
    for (int kt = 0; kt < NK; kt++) {
        CP_WAIT(1);
        __syncthreads();
        if (kt + 2 < NK) load_stage(kt + 2, nslot);
        CP_COMMIT();

        const uint32_t s0 = sb + slot * STAGE_BYTES;
#pragma unroll
        for (int ks = 0; ks < 4; ks++) {
            const uint32_t kx = (uint32_t)ks << 5;
            uint32_t ah[4][4], bh[2][4];
#pragma unroll
            for (int q = 0; q < 2; q++)
                ldsm_x4(bh[q], s0 + OFF_B + (offB[q] ^ kx));
#pragma unroll
            for (int mi = 0; mi < 4; mi++)
                ldsm_x4(ah[mi], s0 + OFF_A + (offA[mi] ^ kx));
#pragma unroll
            for (int mi = 0; mi < 4; mi++)
#pragma unroll
                for (int ni = 0; ni < 4; ni++) {
                    const int q = ni >> 1, h = (ni & 1) * 2;
                    mma_f16(acc[mi][ni], ah[mi], &bh[q][h]);
                }
        }
        slot = (slot == 2) ? 0 : slot + 1;
        nslot = (nslot == 2) ? 0 : nslot + 1;
    }

    // ---- epilogue: + bias ----
#pragma unroll
    for (int mi = 0; mi < 4; mi++) {
        const int r0 = bm + warp_m + mi * 16 + (lane >> 2);
#pragma unroll
        for (int ni = 0; ni < 4; ni++) {
            const int c0 = bn + warp_n + ni * 8 + (lane & 3) * 2;
            const float b0 = bias[c0];
            const float b1 = bias[c0 + 1];
            float2 v0 = make_float2(acc[mi][ni][0] + b0, acc[mi][ni][1] + b1);
            float2 v1 = make_float2(acc[mi][ni][2] + b0, acc[mi][ni][3] + b1);
            *(float2*)(C + (size_t)r0 * N + c0) = v0;
            *(float2*)(C + (size_t)(r0 + 8) * N + c0) = v1;
        }
    }
}

// ===================== launch ==============================================
extern "C" void kernel_launch(void* const* d_in, const int* in_sizes, int n_in,
                              void* d_out, int out_size) {
    const float* x      = (const float*)d_in[0];
    const int*   Wq     = (const int*)d_in[1];
    const float* scales = (const float*)d_in[2];
    const float* zeros  = (const float*)d_in[3];
    const void*  mask   = d_in[4];
    const float* scale2 = (const float*)d_in[5];
    const float* bias   = (const float*)d_in[6];
    float* out = (float*)d_out;

    const int I = in_sizes[5];
    const int O = in_sizes[6];
    const int M = in_sizes[0] / I;
    const int ngroups = in_sizes[2] / O;
    const int G = I / ngroups;

    int nwords = O * I / 4;
    if (nwords > 16384) nwords = 16384;
    detect_mask_kernel<<<1, 1024>>>((const unsigned*)mask, nwords);

    int total4 = M * I / 4;
    cvt_x_kernel<<<(total4 + 511) / 512, 512>>>(x, total4);

    int totalW4 = O * I / 4;
    dequant_kernel<<<(totalW4 + 511) / 512, 512>>>(Wq, scales, zeros,
                                                   mask, scale2, O, I, G);

    cudaFuncSetAttribute(gemm_hmma_kernel,
                         cudaFuncAttributeMaxDynamicSharedMemorySize, SMEM_TOTAL);
    dim3 grid(O / BN, M / BM);
    gemm_hmma_kernel<<<grid, 256, SMEM_TOTAL>>>(bias, out, M, O, I);
}